// round 9
// baseline (speedup 1.0000x reference)
#include <cuda_runtime.h>
#include <cstdint>

// TriplaneDecoder: 2M points, 3x bilinear gather from 512x512x32 planes,
// feature product, MLP 32->64->64->4, sigmoid/exp + bounds mask.
// Output: [c (N*3 floats), sigma (N floats)] concatenated.
//
// R8: occupancy push. h1 spilled to a conflict-free SMEM tile (stride 65),
// layer1 in 16-out chunks / layer2 in 32-out chunks -> regs ~80 -> 3 CTAs/SM
// (24 warps). Weights stay in __constant__ (LDCU). MLP packed f32x2.

#define GRID_N   512
#define NF       32
#define HID      64
#define TPB      256
#define TSTR     65            // tile row stride in floats (odd -> conflict-free)
#define FULLMASK 0xffffffffu

typedef unsigned long long u64;

__constant__ float cW1[NF * HID];    //  8 KB
__constant__ float cW2[HID * HID];   // 16 KB
__constant__ float cW3[HID * 4];     //  1 KB

__device__ __forceinline__ u64 pack2(float x, float y) {
    u64 r; asm("mov.b64 %0, {%1,%2};" : "=l"(r) : "f"(x), "f"(y)); return r;
}
__device__ __forceinline__ void unpack2(u64 v, float& x, float& y) {
    asm("mov.b64 {%0,%1}, %2;" : "=f"(x), "=f"(y) : "l"(v));
}
#define FMA2(d, a, b, c) \
    asm("fma.rn.f32x2 %0, %1, %2, %3;" : "=l"(d) : "l"(a), "l"(b), "l"(c))

extern __shared__ float smemDyn[];   // tile: 8 warps * 32 * TSTR floats

__global__ __launch_bounds__(TPB, 3)
void triplane_decoder_kernel(const float* __restrict__ x,
                             const float* __restrict__ pzh,
                             const float* __restrict__ phw,
                             const float* __restrict__ pzw,
                             float* __restrict__ out, int n) {
    int tid  = threadIdx.x;
    int lane = tid & 31;
    int warp = tid >> 5;
    int i0 = blockIdx.x * TPB + tid;
    int i = min(i0, n - 1);               // clamp so all lanes participate

    float x0 = x[3 * i + 0];
    float x1 = x[3 * i + 1];
    float x2 = x[3 * i + 2];
    bool mask = (fabsf(x0) < 1.0f) && (fabsf(x1) < 1.0f) && (fabsf(x2) < 1.0f);

    // ---- per-point setup: 12 corner offsets (float4 units) + 12 weights ----
    float cus[3] = {x0, x1, x2};
    float cvs[3] = {x1, x2, x0};
    unsigned off4[3][4];
    float    wgt[3][4];
    #pragma unroll
    for (int p = 0; p < 3; p++) {
        const float S = 0.5f * (float)(GRID_N - 1);
        float u = fminf(fmaxf(fmaf(cus[p], S, S), 0.0f), (float)(GRID_N - 1));
        float v = fminf(fmaxf(fmaf(cvs[p], S, S), 0.0f), (float)(GRID_N - 1));
        float fu = floorf(u), fv = floorf(v);
        int u0 = (int)fu, v0 = (int)fv;
        int u1 = min(u0 + 1, GRID_N - 1);
        int v1 = min(v0 + 1, GRID_N - 1);
        float wu = u - fu, wv = v - fv;
        wgt[p][0] = (1.0f - wu) * (1.0f - wv);
        wgt[p][1] = (1.0f - wu) * wv;
        wgt[p][2] = wu * (1.0f - wv);
        wgt[p][3] = wu * wv;
        off4[p][0] = (unsigned)((u0 * GRID_N + v0) * (NF / 4));
        off4[p][1] = (unsigned)((u0 * GRID_N + v1) * (NF / 4));
        off4[p][2] = (unsigned)((u1 * GRID_N + v0) * (NF / 4));
        off4[p][3] = (unsigned)((u1 * GRID_N + v1) * (NF / 4));
    }

    // ---- warp-cooperative coalesced gather + interpolation ----
    // pass t: points (warp-local) 4t..4t+3; lanes 8j+k serve point 4t+j chunk k.
    const float4* bases[3] = {(const float4*)pzh, (const float4*)phw, (const float4*)pzw};
    float* fWarp = smemDyn + warp * 32 * TSTR;
    int j = lane >> 3;
    int k = lane & 7;

    #pragma unroll
    for (int t = 0; t < 8; t++) {
        int src = 4 * t + j;
        float4 acc;
        #pragma unroll
        for (int p = 0; p < 3; p++) {
            float4 pf;
            #pragma unroll
            for (int c = 0; c < 4; c++) {
                unsigned o = __shfl_sync(FULLMASK, off4[p][c], src);
                float    w = __shfl_sync(FULLMASK, wgt[p][c], src);
                float4 d = __ldg(bases[p] + o + k);
                if (c == 0) {
                    pf.x = w * d.x; pf.y = w * d.y; pf.z = w * d.z; pf.w = w * d.w;
                } else {
                    pf.x = fmaf(w, d.x, pf.x); pf.y = fmaf(w, d.y, pf.y);
                    pf.z = fmaf(w, d.z, pf.z); pf.w = fmaf(w, d.w, pf.w);
                }
            }
            if (p == 0) acc = pf;
            else { acc.x *= pf.x; acc.y *= pf.y; acc.z *= pf.z; acc.w *= pf.w; }
        }
        // scalar stores: bank = (4t+j + 4k + c) mod 32 -> conflict-free per c
        float* row = fWarp + src * TSTR + 4 * k;
        row[0] = acc.x; row[1] = acc.y; row[2] = acc.z; row[3] = acc.w;
    }
    __syncwarp();

    // ---- read own features into registers (tile row then recycled for h1) ----
    float* myRow = fWarp + lane * TSTR;
    float feat[NF];
    #pragma unroll
    for (int q = 0; q < NF; q++) feat[q] = myRow[q];
    __syncwarp();   // everyone done reading before rows are overwritten

    // ---- Layer 1: 4 chunks of 16 outputs; relu'd h1 -> SMEM row ----
    #pragma unroll
    for (int c1 = 0; c1 < 4; c1++) {
        u64 acc[8];
        #pragma unroll
        for (int jj = 0; jj < 8; jj++) acc[jj] = 0ULL;
        #pragma unroll
        for (int f = 0; f < NF; f++) {
            u64 aa = pack2(feat[f], feat[f]);
            const ulonglong2* wr = (const ulonglong2*)(cW1 + f * HID + c1 * 16);
            #pragma unroll
            for (int jj = 0; jj < 4; jj++) {
                ulonglong2 wv = wr[jj];
                FMA2(acc[2 * jj + 0], aa, wv.x, acc[2 * jj + 0]);
                FMA2(acc[2 * jj + 1], aa, wv.y, acc[2 * jj + 1]);
            }
        }
        #pragma unroll
        for (int jj = 0; jj < 8; jj++) {
            float a, b; unpack2(acc[jj], a, b);
            myRow[c1 * 16 + 2 * jj + 0] = fmaxf(a, 0.0f);
            myRow[c1 * 16 + 2 * jj + 1] = fmaxf(b, 0.0f);
        }
    }

    // ---- Layer 2: 2 chunks of 32 outputs, fused with Layer 3 ----
    u64 o01 = 0ULL, o23 = 0ULL;
    #pragma unroll
    for (int c2 = 0; c2 < 2; c2++) {
        u64 H2[16];
        #pragma unroll
        for (int jj = 0; jj < 16; jj++) H2[jj] = 0ULL;
        #pragma unroll
        for (int kk = 0; kk < HID; kk++) {
            float a = myRow[kk];
            u64 aa = pack2(a, a);
            const ulonglong2* wr = (const ulonglong2*)(cW2 + kk * HID + c2 * 32);
            #pragma unroll
            for (int jj = 0; jj < 8; jj++) {
                ulonglong2 wv = wr[jj];
                FMA2(H2[2 * jj + 0], aa, wv.x, H2[2 * jj + 0]);
                FMA2(H2[2 * jj + 1], aa, wv.y, H2[2 * jj + 1]);
            }
        }
        // relu + Layer 3 accumulation for these 32 hidden units
        #pragma unroll
        for (int jj = 0; jj < 16; jj++) {
            float a, b; unpack2(H2[jj], a, b);
            a = fmaxf(a, 0.0f); b = fmaxf(b, 0.0f);
            int k0 = c2 * 32 + 2 * jj;
            const ulonglong2* w3 = (const ulonglong2*)(cW3 + k0 * 4);
            ulonglong2 wa = w3[0];
            ulonglong2 wb = w3[1];
            u64 aa = pack2(a, a);
            u64 bb = pack2(b, b);
            FMA2(o01, aa, wa.x, o01);
            FMA2(o23, aa, wa.y, o23);
            FMA2(o01, bb, wb.x, o01);
            FMA2(o23, bb, wb.y, o23);
        }
    }
    float o0, o1, o2, o3;
    unpack2(o01, o0, o1);
    unpack2(o23, o2, o3);

    // ---- activations + masked write ----
    if (i0 < n) {
        float c0 = mask ? 1.0f / (1.0f + __expf(-o0)) : 0.0f;
        float c1 = mask ? 1.0f / (1.0f + __expf(-o1)) : 0.0f;
        float c2 = mask ? 1.0f / (1.0f + __expf(-o2)) : 0.0f;
        float sg = mask ? __expf(o3) : 0.0f;
        out[3 * i0 + 0] = c0;
        out[3 * i0 + 1] = c1;
        out[3 * i0 + 2] = c2;
        out[3 * n + i0] = sg;
    }
}

extern "C" void kernel_launch(void* const* d_in, const int* in_sizes, int n_in,
                              void* d_out, int out_size) {
    const float* x   = (const float*)d_in[0];  // [N,3]
    const float* pzh = (const float*)d_in[1];  // [512,512,32]
    const float* phw = (const float*)d_in[2];
    const float* pzw = (const float*)d_in[3];
    const float* W1  = (const float*)d_in[4];  // [32,64]
    const float* W2  = (const float*)d_in[5];  // [64,64]
    const float* W3  = (const float*)d_in[6];  // [64,4]
    float* out = (float*)d_out;

    // Weights -> constant memory (D2D async copies; graph-capturable, no allocs)
    cudaMemcpyToSymbolAsync(cW1, W1, NF * HID  * sizeof(float), 0,
                            cudaMemcpyDeviceToDevice, 0);
    cudaMemcpyToSymbolAsync(cW2, W2, HID * HID * sizeof(float), 0,
                            cudaMemcpyDeviceToDevice, 0);
    cudaMemcpyToSymbolAsync(cW3, W3, HID * 4   * sizeof(float), 0,
                            cudaMemcpyDeviceToDevice, 0);

    int n = in_sizes[0] / 3;
    int blocks = (n + TPB - 1) / TPB;

    size_t smem = (size_t)(8 * 32 * TSTR) * sizeof(float);
    cudaFuncSetAttribute(triplane_decoder_kernel,
                         cudaFuncAttributeMaxDynamicSharedMemorySize, (int)smem);
    triplane_decoder_kernel<<<blocks, TPB, smem>>>(x, pzh, phw, pzw, out, n);
}

// round 11
// speedup vs baseline: 1.0722x; 1.0722x over previous
#include <cuda_runtime.h>
#include <cstdint>

// TriplaneDecoder: 2M points, 3x bilinear gather from 512x512x32 planes,
// feature product, MLP 32->64->64->4, sigmoid/exp + bounds mask.
// Output: [c (N*3 floats), sigma (N floats)] concatenated.
//
// R9: revert to R6 register-resident MLP (best: 655us); add software
// pipelining: each block does 4 groups of 256 points; gather of group g+1
// (warp-coop, coalesced) is interleaved with layer-1 FMAs of group g via a
// double-buffered SMEM feature tile. Weights in __constant__ (LDCU).

#define GRID_N   512
#define NF       32
#define HID      64
#define TPB      256
#define GROUPS   4
#define FSTR     33            // tile row stride (odd -> conflict-free scalar LDS)
#define TILEW    (32 * FSTR)   // floats per warp per buffer
#define FULLMASK 0xffffffffu

typedef unsigned long long u64;

__constant__ float cW1[NF * HID];    //  8 KB
__constant__ float cW2[HID * HID];   // 16 KB
__constant__ float cW3[HID * 4];     //  1 KB

__device__ __forceinline__ u64 pack2(float x, float y) {
    u64 r; asm("mov.b64 %0, {%1,%2};" : "=l"(r) : "f"(x), "f"(y)); return r;
}
__device__ __forceinline__ void unpack2(u64 v, float& x, float& y) {
    asm("mov.b64 {%0,%1}, %2;" : "=f"(x), "=f"(y) : "l"(v));
}
#define FMA2(d, a, b, c) \
    asm("fma.rn.f32x2 %0, %1, %2, %3;" : "=l"(d) : "l"(a), "l"(b), "l"(c))

extern __shared__ float smemDyn[];   // 2 bufs * 8 warps * TILEW floats

// ---- per-point gather setup: 12 corner offsets (float4 units) + weights ----
__device__ __forceinline__ void computeOffs(const float* __restrict__ x, int i,
                                            unsigned off4[12], float wgt[12],
                                            bool& mask) {
    float x0 = x[3 * i + 0];
    float x1 = x[3 * i + 1];
    float x2 = x[3 * i + 2];
    mask = (fabsf(x0) < 1.0f) && (fabsf(x1) < 1.0f) && (fabsf(x2) < 1.0f);
    float cus[3] = {x0, x1, x2};
    float cvs[3] = {x1, x2, x0};
    #pragma unroll
    for (int p = 0; p < 3; p++) {
        const float S = 0.5f * (float)(GRID_N - 1);
        float u = fminf(fmaxf(fmaf(cus[p], S, S), 0.0f), (float)(GRID_N - 1));
        float v = fminf(fmaxf(fmaf(cvs[p], S, S), 0.0f), (float)(GRID_N - 1));
        float fu = floorf(u), fv = floorf(v);
        int u0 = (int)fu, v0 = (int)fv;
        int u1 = min(u0 + 1, GRID_N - 1);
        int v1 = min(v0 + 1, GRID_N - 1);
        float wu = u - fu, wv = v - fv;
        wgt[p * 4 + 0] = (1.0f - wu) * (1.0f - wv);
        wgt[p * 4 + 1] = (1.0f - wu) * wv;
        wgt[p * 4 + 2] = wu * (1.0f - wv);
        wgt[p * 4 + 3] = wu * wv;
        off4[p * 4 + 0] = (unsigned)((u0 * GRID_N + v0) * (NF / 4));
        off4[p * 4 + 1] = (unsigned)((u0 * GRID_N + v1) * (NF / 4));
        off4[p * 4 + 2] = (unsigned)((u1 * GRID_N + v0) * (NF / 4));
        off4[p * 4 + 3] = (unsigned)((u1 * GRID_N + v1) * (NF / 4));
    }
}

// ---- one warp-cooperative gather pass: points 4t..4t+3 of the group ----
__device__ __forceinline__ void gatherPass(const float4* const bases[3],
                                           const unsigned off4[12],
                                           const float wgt[12],
                                           float* fWarp, int j, int k, int t) {
    int src = 4 * t + j;
    float4 acc;
    #pragma unroll
    for (int p = 0; p < 3; p++) {
        float4 pf;
        #pragma unroll
        for (int c = 0; c < 4; c++) {
            unsigned o = __shfl_sync(FULLMASK, off4[p * 4 + c], src);
            float    w = __shfl_sync(FULLMASK, wgt[p * 4 + c], src);
            float4 d = __ldg(bases[p] + o + k);
            if (c == 0) {
                pf.x = w * d.x; pf.y = w * d.y; pf.z = w * d.z; pf.w = w * d.w;
            } else {
                pf.x = fmaf(w, d.x, pf.x); pf.y = fmaf(w, d.y, pf.y);
                pf.z = fmaf(w, d.z, pf.z); pf.w = fmaf(w, d.w, pf.w);
            }
        }
        if (p == 0) acc = pf;
        else { acc.x *= pf.x; acc.y *= pf.y; acc.z *= pf.z; acc.w *= pf.w; }
    }
    // scalar stores, bank = (src + 4k + c) mod 32 -> conflict-free
    float* row = fWarp + src * FSTR + 4 * k;
    row[0] = acc.x; row[1] = acc.y; row[2] = acc.z; row[3] = acc.w;
}

// ---- layer-1 chunk: channels 4t..4t+3 read from tile row, 128 FMA2 ----
__device__ __forceinline__ void layer1Chunk(const float* myRow, int t, u64 H1[32]) {
    #pragma unroll
    for (int c = 0; c < 4; c++) {
        int f = 4 * t + c;
        float fv = myRow[f];
        u64 aa = pack2(fv, fv);
        const ulonglong2* wr = (const ulonglong2*)(cW1 + f * HID);
        #pragma unroll
        for (int jj = 0; jj < 16; jj++) {
            ulonglong2 wv = wr[jj];
            FMA2(H1[2 * jj + 0], aa, wv.x, H1[2 * jj + 0]);
            FMA2(H1[2 * jj + 1], aa, wv.y, H1[2 * jj + 1]);
        }
    }
}

__global__ __launch_bounds__(TPB, 2)
void triplane_decoder_kernel(const float* __restrict__ x,
                             const float* __restrict__ pzh,
                             const float* __restrict__ phw,
                             const float* __restrict__ pzw,
                             float* __restrict__ out, int n) {
    int tid  = threadIdx.x;
    int lane = tid & 31;
    int warp = tid >> 5;
    int base = blockIdx.x * TPB * GROUPS;

    const float4* bases[3] = {(const float4*)pzh, (const float4*)phw, (const float4*)pzw};
    int j = lane >> 3;
    int k = lane & 7;

    unsigned off4[12];
    float    wgt[12];
    bool maskNext, maskCur;

    // ---- prologue: gather group 0 into buffer 0 ----
    int iNext = min(base + tid, n - 1);
    computeOffs(x, iNext, off4, wgt, maskNext);
    {
        float* fW = smemDyn + warp * TILEW;
        #pragma unroll
        for (int t = 0; t < 8; t++)
            gatherPass(bases, off4, wgt, fW, j, k, t);
    }
    __syncwarp();

    int buf = 0;
    for (int g = 0; g < GROUPS; g++) {
        maskCur = maskNext;
        int i0 = base + g * TPB + tid;           // this thread's point (may be >= n)

        if (g + 1 < GROUPS) {
            int i1 = min(base + (g + 1) * TPB + tid, n - 1);
            computeOffs(x, i1, off4, wgt, maskNext);
        }

        const float* myRow = smemDyn + buf * 8 * TILEW + warp * TILEW + lane * FSTR;

        // ---- layer 1 interleaved with gather of next group ----
        u64 H1[HID / 2];
        #pragma unroll
        for (int jj = 0; jj < HID / 2; jj++) H1[jj] = 0ULL;

        if (g + 1 < GROUPS) {
            float* fWNext = smemDyn + (buf ^ 1) * 8 * TILEW + warp * TILEW;
            #pragma unroll
            for (int t = 0; t < 8; t++) {
                gatherPass(bases, off4, wgt, fWNext, j, k, t);
                layer1Chunk(myRow, t, H1);
            }
        } else {
            #pragma unroll
            for (int t = 0; t < 8; t++)
                layer1Chunk(myRow, t, H1);
        }
        __syncwarp();

        // relu on h1
        #pragma unroll
        for (int jj = 0; jj < HID / 2; jj++) {
            float a, b; unpack2(H1[jj], a, b);
            H1[jj] = pack2(fmaxf(a, 0.0f), fmaxf(b, 0.0f));
        }

        // ---- Layer 2 (chunks of 16 outputs) fused with Layer 3 ----
        u64 o01 = 0ULL, o23 = 0ULL;
        #pragma unroll
        for (int cc = 0; cc < 4; cc++) {
            u64 H2[8];
            #pragma unroll
            for (int jj = 0; jj < 8; jj++) H2[jj] = 0ULL;
            #pragma unroll
            for (int kk = 0; kk < HID / 2; kk++) {
                float a, b; unpack2(H1[kk], a, b);
                u64 aa = pack2(a, a);
                u64 bb = pack2(b, b);
                const ulonglong2* wA = (const ulonglong2*)(cW2 + (2 * kk + 0) * HID + cc * 16);
                const ulonglong2* wB = (const ulonglong2*)(cW2 + (2 * kk + 1) * HID + cc * 16);
                #pragma unroll
                for (int jj = 0; jj < 4; jj++) {
                    ulonglong2 wv = wA[jj];
                    FMA2(H2[2 * jj + 0], aa, wv.x, H2[2 * jj + 0]);
                    FMA2(H2[2 * jj + 1], aa, wv.y, H2[2 * jj + 1]);
                }
                #pragma unroll
                for (int jj = 0; jj < 4; jj++) {
                    ulonglong2 wv = wB[jj];
                    FMA2(H2[2 * jj + 0], bb, wv.x, H2[2 * jj + 0]);
                    FMA2(H2[2 * jj + 1], bb, wv.y, H2[2 * jj + 1]);
                }
            }
            #pragma unroll
            for (int jj = 0; jj < 8; jj++) {
                float a, b; unpack2(H2[jj], a, b);
                a = fmaxf(a, 0.0f); b = fmaxf(b, 0.0f);
                int k0 = cc * 16 + 2 * jj;
                const ulonglong2* w3 = (const ulonglong2*)(cW3 + k0 * 4);
                ulonglong2 wa = w3[0];
                ulonglong2 wb = w3[1];
                u64 aa = pack2(a, a);
                u64 bb = pack2(b, b);
                FMA2(o01, aa, wa.x, o01);
                FMA2(o23, aa, wa.y, o23);
                FMA2(o01, bb, wb.x, o01);
                FMA2(o23, bb, wb.y, o23);
            }
        }
        float o0, o1, o2, o3;
        unpack2(o01, o0, o1);
        unpack2(o23, o2, o3);

        // ---- activations + masked write ----
        if (i0 < n) {
            float c0 = maskCur ? 1.0f / (1.0f + __expf(-o0)) : 0.0f;
            float c1 = maskCur ? 1.0f / (1.0f + __expf(-o1)) : 0.0f;
            float c2 = maskCur ? 1.0f / (1.0f + __expf(-o2)) : 0.0f;
            float sg = maskCur ? __expf(o3) : 0.0f;
            out[3 * i0 + 0] = c0;
            out[3 * i0 + 1] = c1;
            out[3 * i0 + 2] = c2;
            out[3 * n + i0] = sg;
        }
        buf ^= 1;
    }
}

extern "C" void kernel_launch(void* const* d_in, const int* in_sizes, int n_in,
                              void* d_out, int out_size) {
    const float* x   = (const float*)d_in[0];  // [N,3]
    const float* pzh = (const float*)d_in[1];  // [512,512,32]
    const float* phw = (const float*)d_in[2];
    const float* pzw = (const float*)d_in[3];
    const float* W1  = (const float*)d_in[4];  // [32,64]
    const float* W2  = (const float*)d_in[5];  // [64,64]
    const float* W3  = (const float*)d_in[6];  // [64,4]
    float* out = (float*)d_out;

    // Weights -> constant memory (D2D async copies; graph-capturable, no allocs)
    cudaMemcpyToSymbolAsync(cW1, W1, NF * HID  * sizeof(float), 0,
                            cudaMemcpyDeviceToDevice, 0);
    cudaMemcpyToSymbolAsync(cW2, W2, HID * HID * sizeof(float), 0,
                            cudaMemcpyDeviceToDevice, 0);
    cudaMemcpyToSymbolAsync(cW3, W3, HID * 4   * sizeof(float), 0,
                            cudaMemcpyDeviceToDevice, 0);

    int n = in_sizes[0] / 3;
    int ptsPerBlock = TPB * GROUPS;
    int blocks = (n + ptsPerBlock - 1) / ptsPerBlock;

    size_t smem = (size_t)(2 * 8 * TILEW) * sizeof(float);
    cudaFuncSetAttribute(triplane_decoder_kernel,
                         cudaFuncAttributeMaxDynamicSharedMemorySize, (int)smem);
    triplane_decoder_kernel<<<blocks, TPB, smem>>>(x, pzh, phw, pzw, out, n);
}

// round 12
// speedup vs baseline: 1.5174x; 1.4151x over previous
#include <cuda_runtime.h>
#include <cstdint>

// TriplaneDecoder: 2M points, 3x bilinear gather from 512x512x32 planes,
// feature product, MLP 32->64->64->4, sigmoid/exp + bounds mask.
// Output: [c (N*3 floats), sigma (N floats)] concatenated.
//
// R11 = R6 (best, 655us) with ONE change: W2 moved from __constant__ to
// static SMEM. R6 was constant-port bound (1600 LDC.128 x floor 8 = 12800
// cyc/warp vs 6400 FMA2 cyc -> measured fma=50%). Splitting weight traffic
// (W1+W3 on const port: 4608 cyc; W2 on LDS broadcast: ~2048 cyc) makes the
// packed-FMA pipe the binding resource.

#define GRID_N   512
#define NF       32
#define HID      64
#define TPB      256
#define FSTR     36            // feature row stride in floats (padded, 16B aligned)
#define FULLMASK 0xffffffffu

typedef unsigned long long u64;

__constant__ float cW1[NF * HID];    //  8 KB (const port)
__constant__ float cW3[HID * 4];     //  1 KB (const port)

__device__ __forceinline__ u64 pack2(float x, float y) {
    u64 r; asm("mov.b64 %0, {%1,%2};" : "=l"(r) : "f"(x), "f"(y)); return r;
}
__device__ __forceinline__ void unpack2(u64 v, float& x, float& y) {
    asm("mov.b64 {%0,%1}, %2;" : "=f"(x), "=f"(y) : "l"(v));
}
#define FMA2(d, a, b, c) \
    asm("fma.rn.f32x2 %0, %1, %2, %3;" : "=l"(d) : "l"(a), "l"(b), "l"(c))

extern __shared__ float smemDyn[];   // feat tile: 8 warps * 32 * FSTR floats

__global__ __launch_bounds__(TPB, 2)
void triplane_decoder_kernel(const float* __restrict__ x,
                             const float* __restrict__ pzh,
                             const float* __restrict__ phw,
                             const float* __restrict__ pzw,
                             const float* __restrict__ W2,
                             float* __restrict__ out, int n) {
    __shared__ __align__(16) float sW2[HID * HID];   // 16 KB (LDS broadcast)
    float* sFeat = smemDyn;

    int tid  = threadIdx.x;
    for (int k = tid; k < HID * HID; k += TPB) sW2[k] = W2[k];
    __syncthreads();

    int lane = tid & 31;
    int warp = tid >> 5;
    int i0 = blockIdx.x * TPB + tid;
    int i = min(i0, n - 1);               // clamp so all lanes participate

    float x0 = x[3 * i + 0];
    float x1 = x[3 * i + 1];
    float x2 = x[3 * i + 2];
    bool mask = (fabsf(x0) < 1.0f) && (fabsf(x1) < 1.0f) && (fabsf(x2) < 1.0f);

    // ---- per-point setup: 12 corner offsets (float4 units) + 12 weights ----
    float cus[3] = {x0, x1, x2};
    float cvs[3] = {x1, x2, x0};
    unsigned off4[3][4];
    float    wgt[3][4];
    #pragma unroll
    for (int p = 0; p < 3; p++) {
        const float S = 0.5f * (float)(GRID_N - 1);
        float u = fminf(fmaxf(fmaf(cus[p], S, S), 0.0f), (float)(GRID_N - 1));
        float v = fminf(fmaxf(fmaf(cvs[p], S, S), 0.0f), (float)(GRID_N - 1));
        float fu = floorf(u), fv = floorf(v);
        int u0 = (int)fu, v0 = (int)fv;
        int u1 = min(u0 + 1, GRID_N - 1);
        int v1 = min(v0 + 1, GRID_N - 1);
        float wu = u - fu, wv = v - fv;
        wgt[p][0] = (1.0f - wu) * (1.0f - wv);
        wgt[p][1] = (1.0f - wu) * wv;
        wgt[p][2] = wu * (1.0f - wv);
        wgt[p][3] = wu * wv;
        off4[p][0] = (unsigned)((u0 * GRID_N + v0) * (NF / 4));
        off4[p][1] = (unsigned)((u0 * GRID_N + v1) * (NF / 4));
        off4[p][2] = (unsigned)((u1 * GRID_N + v0) * (NF / 4));
        off4[p][3] = (unsigned)((u1 * GRID_N + v1) * (NF / 4));
    }

    // ---- warp-cooperative coalesced gather + interpolation ----
    // pass t: points (warp-local) 4t..4t+3; lanes 8j+k serve point 4t+j chunk k.
    const float4* bases[3] = {(const float4*)pzh, (const float4*)phw, (const float4*)pzw};
    float* fWarp = sFeat + warp * 32 * FSTR;
    int j = lane >> 3;
    int k = lane & 7;

    #pragma unroll
    for (int t = 0; t < 8; t++) {
        int src = 4 * t + j;
        float4 acc;
        #pragma unroll
        for (int p = 0; p < 3; p++) {
            float4 pf;
            #pragma unroll
            for (int c = 0; c < 4; c++) {
                unsigned o = __shfl_sync(FULLMASK, off4[p][c], src);
                float    w = __shfl_sync(FULLMASK, wgt[p][c], src);
                float4 d = __ldg(bases[p] + o + k);
                if (c == 0) {
                    pf.x = w * d.x; pf.y = w * d.y; pf.z = w * d.z; pf.w = w * d.w;
                } else {
                    pf.x = fmaf(w, d.x, pf.x); pf.y = fmaf(w, d.y, pf.y);
                    pf.z = fmaf(w, d.z, pf.z); pf.w = fmaf(w, d.w, pf.w);
                }
            }
            if (p == 0) acc = pf;
            else { acc.x *= pf.x; acc.y *= pf.y; acc.z *= pf.z; acc.w *= pf.w; }
        }
        *(float4*)(fWarp + src * FSTR + k * 4) = acc;
    }
    __syncwarp();

    // ---- read back own features ----
    float feat[NF];
    const float* myRow = fWarp + lane * FSTR;
    #pragma unroll
    for (int q = 0; q < NF / 4; q++) {
        float4 v = *(const float4*)(myRow + 4 * q);
        feat[4 * q + 0] = v.x; feat[4 * q + 1] = v.y;
        feat[4 * q + 2] = v.z; feat[4 * q + 3] = v.w;
    }

    // ---- Layer 1: h1 = relu(feat @ W1), accumulated as 32 packed pairs ----
    u64 H1[HID / 2];
    #pragma unroll
    for (int jj = 0; jj < HID / 2; jj++) H1[jj] = 0ULL;
    #pragma unroll
    for (int f = 0; f < NF; f++) {
        u64 aa = pack2(feat[f], feat[f]);
        const ulonglong2* wr = (const ulonglong2*)(cW1 + f * HID);
        #pragma unroll
        for (int jj = 0; jj < 16; jj++) {
            ulonglong2 wv = wr[jj];
            FMA2(H1[2 * jj + 0], aa, wv.x, H1[2 * jj + 0]);
            FMA2(H1[2 * jj + 1], aa, wv.y, H1[2 * jj + 1]);
        }
    }
    #pragma unroll
    for (int jj = 0; jj < HID / 2; jj++) {
        float a, b; unpack2(H1[jj], a, b);
        H1[jj] = pack2(fmaxf(a, 0.0f), fmaxf(b, 0.0f));
    }

    // ---- Layer 2 (chunks of 16 outputs) fused with Layer 3 ----
    u64 o01 = 0ULL, o23 = 0ULL;
    #pragma unroll
    for (int cc = 0; cc < 4; cc++) {
        u64 H2[8];
        #pragma unroll
        for (int jj = 0; jj < 8; jj++) H2[jj] = 0ULL;
        #pragma unroll
        for (int kk = 0; kk < HID / 2; kk++) {
            float a, b; unpack2(H1[kk], a, b);
            u64 aa = pack2(a, a);
            u64 bb = pack2(b, b);
            const ulonglong2* wA = (const ulonglong2*)(sW2 + (2 * kk + 0) * HID + cc * 16);
            const ulonglong2* wB = (const ulonglong2*)(sW2 + (2 * kk + 1) * HID + cc * 16);
            #pragma unroll
            for (int jj = 0; jj < 4; jj++) {
                ulonglong2 wv = wA[jj];
                FMA2(H2[2 * jj + 0], aa, wv.x, H2[2 * jj + 0]);
                FMA2(H2[2 * jj + 1], aa, wv.y, H2[2 * jj + 1]);
            }
            #pragma unroll
            for (int jj = 0; jj < 4; jj++) {
                ulonglong2 wv = wB[jj];
                FMA2(H2[2 * jj + 0], bb, wv.x, H2[2 * jj + 0]);
                FMA2(H2[2 * jj + 1], bb, wv.y, H2[2 * jj + 1]);
            }
        }
        #pragma unroll
        for (int jj = 0; jj < 8; jj++) {
            float a, b; unpack2(H2[jj], a, b);
            a = fmaxf(a, 0.0f); b = fmaxf(b, 0.0f);
            int k0 = cc * 16 + 2 * jj;
            const ulonglong2* w3 = (const ulonglong2*)(cW3 + k0 * 4);
            ulonglong2 wa = w3[0];
            ulonglong2 wb = w3[1];
            u64 aa = pack2(a, a);
            u64 bb = pack2(b, b);
            FMA2(o01, aa, wa.x, o01);
            FMA2(o23, aa, wa.y, o23);
            FMA2(o01, bb, wb.x, o01);
            FMA2(o23, bb, wb.y, o23);
        }
    }
    float o0, o1, o2, o3;
    unpack2(o01, o0, o1);
    unpack2(o23, o2, o3);

    // ---- activations + masked write ----
    if (i0 < n) {
        float c0 = mask ? 1.0f / (1.0f + __expf(-o0)) : 0.0f;
        float c1 = mask ? 1.0f / (1.0f + __expf(-o1)) : 0.0f;
        float c2 = mask ? 1.0f / (1.0f + __expf(-o2)) : 0.0f;
        float sg = mask ? __expf(o3) : 0.0f;
        out[3 * i0 + 0] = c0;
        out[3 * i0 + 1] = c1;
        out[3 * i0 + 2] = c2;
        out[3 * n + i0] = sg;
    }
}

extern "C" void kernel_launch(void* const* d_in, const int* in_sizes, int n_in,
                              void* d_out, int out_size) {
    const float* x   = (const float*)d_in[0];  // [N,3]
    const float* pzh = (const float*)d_in[1];  // [512,512,32]
    const float* phw = (const float*)d_in[2];
    const float* pzw = (const float*)d_in[3];
    const float* W1  = (const float*)d_in[4];  // [32,64]
    const float* W2  = (const float*)d_in[5];  // [64,64]
    const float* W3  = (const float*)d_in[6];  // [64,4]
    float* out = (float*)d_out;

    // W1/W3 -> constant memory (D2D async copies; graph-capturable, no allocs)
    cudaMemcpyToSymbolAsync(cW1, W1, NF * HID  * sizeof(float), 0,
                            cudaMemcpyDeviceToDevice, 0);
    cudaMemcpyToSymbolAsync(cW3, W3, HID * 4   * sizeof(float), 0,
                            cudaMemcpyDeviceToDevice, 0);

    int n = in_sizes[0] / 3;
    int blocks = (n + TPB - 1) / TPB;

    size_t smem = (size_t)(8 * 32 * FSTR) * sizeof(float);
    cudaFuncSetAttribute(triplane_decoder_kernel,
                         cudaFuncAttributeMaxDynamicSharedMemorySize, (int)smem);
    triplane_decoder_kernel<<<blocks, TPB, smem>>>(x, pzh, phw, pzw, W2, out, n);
}

// round 14
// speedup vs baseline: 1.5445x; 1.0179x over previous
#include <cuda_runtime.h>
#include <cstdint>

// TriplaneDecoder R13 = R6 (best, 655us) + pipelined gather (3-chunk register
// lookahead ring over 24 (pass,plane) chunks) + packed-f32x2 interpolation
// (bit-identical per-lane math). MLP (register-resident, packed f32x2,
// __constant__ weights) untouched.
// Output: [c (N*3 floats), sigma (N floats)] concatenated.

#define GRID_N   512
#define NF       32
#define HID      64
#define TPB      256
#define FSTR     36            // feature row stride in floats (16B aligned)
#define FULLMASK 0xffffffffu

typedef unsigned long long u64;

__constant__ float cW1[NF * HID];    //  8 KB
__constant__ float cW2[HID * HID];   // 16 KB
__constant__ float cW3[HID * 4];     //  1 KB

__device__ __forceinline__ u64 pack2(float x, float y) {
    u64 r; asm("mov.b64 %0, {%1,%2};" : "=l"(r) : "f"(x), "f"(y)); return r;
}
__device__ __forceinline__ void unpack2(u64 v, float& x, float& y) {
    asm("mov.b64 {%0,%1}, %2;" : "=f"(x), "=f"(y) : "l"(v));
}
#define FMA2(d, a, b, c) \
    asm("fma.rn.f32x2 %0, %1, %2, %3;" : "=l"(d) : "l"(a), "l"(b), "l"(c))
#define MUL2(d, a, b) \
    asm("mul.rn.f32x2 %0, %1, %2;" : "=l"(d) : "l"(a), "l"(b))

extern __shared__ float smemDyn[];   // feat tile: 8 warps * 32 * FSTR floats

__global__ __launch_bounds__(TPB, 2)
void triplane_decoder_kernel(const float* __restrict__ x,
                             const float* __restrict__ pzh,
                             const float* __restrict__ phw,
                             const float* __restrict__ pzw,
                             float* __restrict__ out, int n) {
    float* sFeat = smemDyn;

    int tid  = threadIdx.x;
    int lane = tid & 31;
    int warp = tid >> 5;
    int i0 = blockIdx.x * TPB + tid;
    int i = min(i0, n - 1);               // clamp so all lanes participate

    float x0 = x[3 * i + 0];
    float x1 = x[3 * i + 1];
    float x2 = x[3 * i + 2];
    bool mask = (fabsf(x0) < 1.0f) && (fabsf(x1) < 1.0f) && (fabsf(x2) < 1.0f);

    // ---- per-point setup: 12 corner offsets (float4 units) + 12 weights ----
    float cus[3] = {x0, x1, x2};
    float cvs[3] = {x1, x2, x0};
    unsigned off4[3][4];
    float    wgt[3][4];
    #pragma unroll
    for (int p = 0; p < 3; p++) {
        const float S = 0.5f * (float)(GRID_N - 1);
        float u = fminf(fmaxf(fmaf(cus[p], S, S), 0.0f), (float)(GRID_N - 1));
        float v = fminf(fmaxf(fmaf(cvs[p], S, S), 0.0f), (float)(GRID_N - 1));
        float fu = floorf(u), fv = floorf(v);
        int u0 = (int)fu, v0 = (int)fv;
        int u1 = min(u0 + 1, GRID_N - 1);
        int v1 = min(v0 + 1, GRID_N - 1);
        float wu = u - fu, wv = v - fv;
        wgt[p][0] = (1.0f - wu) * (1.0f - wv);
        wgt[p][1] = (1.0f - wu) * wv;
        wgt[p][2] = wu * (1.0f - wv);
        wgt[p][3] = wu * wv;
        off4[p][0] = (unsigned)((u0 * GRID_N + v0) * (NF / 4));
        off4[p][1] = (unsigned)((u0 * GRID_N + v1) * (NF / 4));
        off4[p][2] = (unsigned)((u1 * GRID_N + v0) * (NF / 4));
        off4[p][3] = (unsigned)((u1 * GRID_N + v1) * (NF / 4));
    }

    // ---- pipelined warp-cooperative gather ----
    // chunk c (0..23): pass t=c/3 (points 4t..4t+3), plane p=c%3.
    // lanes 8j+k: j = point-in-pass, k = float4 chunk of the 128B row.
    // 4-slot register ring, loads issued 3 chunks ahead of interp.
    const float4* bases[3] = {(const float4*)pzh, (const float4*)phw, (const float4*)pzw};
    float* fWarp = sFeat + warp * 32 * FSTR;
    int j = lane >> 3;
    int k = lane & 7;

    float4 ring[4][4];
    u64 accLo = 0ULL, accHi = 0ULL;

    #define LOAD_CHUNK(c) do {                                                \
        const int _t = (c) / 3, _p = (c) % 3, _s = (c) & 3;                   \
        int _src = 4 * _t + j;                                                \
        _Pragma("unroll")                                                     \
        for (int q = 0; q < 4; q++) {                                         \
            unsigned o = __shfl_sync(FULLMASK, off4[_p][q], _src);            \
            ring[_s][q] = __ldg(bases[_p] + o + k);                           \
        }                                                                     \
    } while (0)

    #define INTERP_CHUNK(c) do {                                              \
        const int _t = (c) / 3, _p = (c) % 3, _s = (c) & 3;                   \
        int _src = 4 * _t + j;                                                \
        u64 pflo, pfhi;                                                       \
        _Pragma("unroll")                                                     \
        for (int q = 0; q < 4; q++) {                                         \
            float w = __shfl_sync(FULLMASK, wgt[_p][q], _src);                \
            u64 ww = pack2(w, w);                                             \
            ulonglong2 d = *(ulonglong2*)&ring[_s][q];                        \
            if (q == 0) { MUL2(pflo, d.x, ww); MUL2(pfhi, d.y, ww); }         \
            else { FMA2(pflo, d.x, ww, pflo); FMA2(pfhi, d.y, ww, pfhi); }    \
        }                                                                     \
        if (_p == 0) { accLo = pflo; accHi = pfhi; }                          \
        else { MUL2(accLo, accLo, pflo); MUL2(accHi, accHi, pfhi); }          \
        if (_p == 2) {                                                        \
            ulonglong2* dst = (ulonglong2*)(fWarp + _src * FSTR + k * 4);     \
            ulonglong2 v; v.x = accLo; v.y = accHi;                           \
            *dst = v;                                                         \
        }                                                                     \
    } while (0)

    LOAD_CHUNK(0);
    LOAD_CHUNK(1);
    LOAD_CHUNK(2);
    #pragma unroll
    for (int c = 0; c < 24; c++) {
        if (c + 3 < 24) {
            switch (c + 3) {   // compile-time after unroll
                case 3:  LOAD_CHUNK(3);  break; case 4:  LOAD_CHUNK(4);  break;
                case 5:  LOAD_CHUNK(5);  break; case 6:  LOAD_CHUNK(6);  break;
                case 7:  LOAD_CHUNK(7);  break; case 8:  LOAD_CHUNK(8);  break;
                case 9:  LOAD_CHUNK(9);  break; case 10: LOAD_CHUNK(10); break;
                case 11: LOAD_CHUNK(11); break; case 12: LOAD_CHUNK(12); break;
                case 13: LOAD_CHUNK(13); break; case 14: LOAD_CHUNK(14); break;
                case 15: LOAD_CHUNK(15); break; case 16: LOAD_CHUNK(16); break;
                case 17: LOAD_CHUNK(17); break; case 18: LOAD_CHUNK(18); break;
                case 19: LOAD_CHUNK(19); break; case 20: LOAD_CHUNK(20); break;
                case 21: LOAD_CHUNK(21); break; case 22: LOAD_CHUNK(22); break;
                case 23: LOAD_CHUNK(23); break;
            }
        }
        switch (c) {
            case 0:  INTERP_CHUNK(0);  break; case 1:  INTERP_CHUNK(1);  break;
            case 2:  INTERP_CHUNK(2);  break; case 3:  INTERP_CHUNK(3);  break;
            case 4:  INTERP_CHUNK(4);  break; case 5:  INTERP_CHUNK(5);  break;
            case 6:  INTERP_CHUNK(6);  break; case 7:  INTERP_CHUNK(7);  break;
            case 8:  INTERP_CHUNK(8);  break; case 9:  INTERP_CHUNK(9);  break;
            case 10: INTERP_CHUNK(10); break; case 11: INTERP_CHUNK(11); break;
            case 12: INTERP_CHUNK(12); break; case 13: INTERP_CHUNK(13); break;
            case 14: INTERP_CHUNK(14); break; case 15: INTERP_CHUNK(15); break;
            case 16: INTERP_CHUNK(16); break; case 17: INTERP_CHUNK(17); break;
            case 18: INTERP_CHUNK(18); break; case 19: INTERP_CHUNK(19); break;
            case 20: INTERP_CHUNK(20); break; case 21: INTERP_CHUNK(21); break;
            case 22: INTERP_CHUNK(22); break; case 23: INTERP_CHUNK(23); break;
        }
    }
    __syncwarp();

    // ---- read back own features ----
    float feat[NF];
    const float* myRow = fWarp + lane * FSTR;
    #pragma unroll
    for (int q = 0; q < NF / 4; q++) {
        float4 v = *(const float4*)(myRow + 4 * q);
        feat[4 * q + 0] = v.x; feat[4 * q + 1] = v.y;
        feat[4 * q + 2] = v.z; feat[4 * q + 3] = v.w;
    }

    // ---- Layer 1: h1 = relu(feat @ W1), accumulated as 32 packed pairs ----
    u64 H1[HID / 2];
    #pragma unroll
    for (int jj = 0; jj < HID / 2; jj++) H1[jj] = 0ULL;
    #pragma unroll
    for (int f = 0; f < NF; f++) {
        u64 aa = pack2(feat[f], feat[f]);
        const ulonglong2* wr = (const ulonglong2*)(cW1 + f * HID);
        #pragma unroll
        for (int jj = 0; jj < 16; jj++) {
            ulonglong2 wv = wr[jj];
            FMA2(H1[2 * jj + 0], aa, wv.x, H1[2 * jj + 0]);
            FMA2(H1[2 * jj + 1], aa, wv.y, H1[2 * jj + 1]);
        }
    }
    #pragma unroll
    for (int jj = 0; jj < HID / 2; jj++) {
        float a, b; unpack2(H1[jj], a, b);
        H1[jj] = pack2(fmaxf(a, 0.0f), fmaxf(b, 0.0f));
    }

    // ---- Layer 2 (chunks of 16 outputs) fused with Layer 3 ----
    u64 o01 = 0ULL, o23 = 0ULL;
    #pragma unroll
    for (int cc = 0; cc < 4; cc++) {
        u64 H2[8];
        #pragma unroll
        for (int jj = 0; jj < 8; jj++) H2[jj] = 0ULL;
        #pragma unroll
        for (int kk = 0; kk < HID / 2; kk++) {
            float a, b; unpack2(H1[kk], a, b);
            u64 aa = pack2(a, a);
            u64 bb = pack2(b, b);
            const ulonglong2* wA = (const ulonglong2*)(cW2 + (2 * kk + 0) * HID + cc * 16);
            const ulonglong2* wB = (const ulonglong2*)(cW2 + (2 * kk + 1) * HID + cc * 16);
            #pragma unroll
            for (int jj = 0; jj < 4; jj++) {
                ulonglong2 wv = wA[jj];
                FMA2(H2[2 * jj + 0], aa, wv.x, H2[2 * jj + 0]);
                FMA2(H2[2 * jj + 1], aa, wv.y, H2[2 * jj + 1]);
            }
            #pragma unroll
            for (int jj = 0; jj < 4; jj++) {
                ulonglong2 wv = wB[jj];
                FMA2(H2[2 * jj + 0], bb, wv.x, H2[2 * jj + 0]);
                FMA2(H2[2 * jj + 1], bb, wv.y, H2[2 * jj + 1]);
            }
        }
        #pragma unroll
        for (int jj = 0; jj < 8; jj++) {
            float a, b; unpack2(H2[jj], a, b);
            a = fmaxf(a, 0.0f); b = fmaxf(b, 0.0f);
            int k0 = cc * 16 + 2 * jj;
            const ulonglong2* w3 = (const ulonglong2*)(cW3 + k0 * 4);
            ulonglong2 wa = w3[0];
            ulonglong2 wb = w3[1];
            u64 aa = pack2(a, a);
            u64 bb = pack2(b, b);
            FMA2(o01, aa, wa.x, o01);
            FMA2(o23, aa, wa.y, o23);
            FMA2(o01, bb, wb.x, o01);
            FMA2(o23, bb, wb.y, o23);
        }
    }
    float o0, o1, o2, o3;
    unpack2(o01, o0, o1);
    unpack2(o23, o2, o3);

    // ---- activations + masked write ----
    if (i0 < n) {
        float c0 = mask ? 1.0f / (1.0f + __expf(-o0)) : 0.0f;
        float c1 = mask ? 1.0f / (1.0f + __expf(-o1)) : 0.0f;
        float c2 = mask ? 1.0f / (1.0f + __expf(-o2)) : 0.0f;
        float sg = mask ? __expf(o3) : 0.0f;
        out[3 * i0 + 0] = c0;
        out[3 * i0 + 1] = c1;
        out[3 * i0 + 2] = c2;
        out[3 * n + i0] = sg;
    }
}

extern "C" void kernel_launch(void* const* d_in, const int* in_sizes, int n_in,
                              void* d_out, int out_size) {
    const float* x   = (const float*)d_in[0];  // [N,3]
    const float* pzh = (const float*)d_in[1];  // [512,512,32]
    const float* phw = (const float*)d_in[2];
    const float* pzw = (const float*)d_in[3];
    const float* W1  = (const float*)d_in[4];  // [32,64]
    const float* W2  = (const float*)d_in[5];  // [64,64]
    const float* W3  = (const float*)d_in[6];  // [64,4]
    float* out = (float*)d_out;

    // Weights -> constant memory (D2D async copies; graph-capturable, no allocs)
    cudaMemcpyToSymbolAsync(cW1, W1, NF * HID  * sizeof(float), 0,
                            cudaMemcpyDeviceToDevice, 0);
    cudaMemcpyToSymbolAsync(cW2, W2, HID * HID * sizeof(float), 0,
                            cudaMemcpyDeviceToDevice, 0);
    cudaMemcpyToSymbolAsync(cW3, W3, HID * 4   * sizeof(float), 0,
                            cudaMemcpyDeviceToDevice, 0);

    int n = in_sizes[0] / 3;
    int blocks = (n + TPB - 1) / TPB;

    size_t smem = (size_t)(8 * 32 * FSTR) * sizeof(float);
    cudaFuncSetAttribute(triplane_decoder_kernel,
                         cudaFuncAttributeMaxDynamicSharedMemorySize, (int)smem);
    triplane_decoder_kernel<<<blocks, TPB, smem>>>(x, pzh, phw, pzw, out, n);
}

// round 15
// speedup vs baseline: 2.7779x; 1.7985x over previous
#include <cuda_runtime.h>
#include <cuda_bf16.h>
#include <cstdint>

// TriplaneDecoder R14: MLP on the legacy tensor pipe via mma.sync bf16
// (m16n8k16), hi/lo split for fp32-grade precision. Gather = R6 warp-coop
// coalesced (unchanged). B fragments for W1/W2 prebuilt in SMEM per CTA.
// Output: [c (N*3 floats), sigma (N floats)] concatenated.

#define GRID_N   512
#define NF       32
#define HID      64
#define TPB      256
#define FSTR     36            // feat tile row stride (col 32 = mask flag)
#define FULLMASK 0xffffffffu

__device__ __forceinline__ uint32_t bfp(float a, float b) {
    unsigned short ha = __bfloat16_as_ushort(__float2bfloat16(a));
    unsigned short hb = __bfloat16_as_ushort(__float2bfloat16(b));
    return (uint32_t)ha | ((uint32_t)hb << 16);
}
__device__ __forceinline__ float bfres(float a) {
    return a - __bfloat162float(__float2bfloat16(a));
}

#define MMA_BF16(d0, d1, d2, d3, a0, a1, a2, a3, b0, b1)                      \
    asm volatile("mma.sync.aligned.m16n8k16.row.col.f32.bf16.bf16.f32 "       \
        "{%0,%1,%2,%3}, {%4,%5,%6,%7}, {%8,%9}, {%0,%1,%2,%3};"               \
        : "+f"(d0), "+f"(d1), "+f"(d2), "+f"(d3)                              \
        : "r"(a0), "r"(a1), "r"(a2), "r"(a3), "r"(b0), "r"(b1))

extern __shared__ float smemDyn[];   // feat tile: 8 warps * 32 * FSTR floats

__global__ __launch_bounds__(TPB, 2)
void triplane_decoder_kernel(const float* __restrict__ x,
                             const float* __restrict__ pzh,
                             const float* __restrict__ phw,
                             const float* __restrict__ pzw,
                             const float* __restrict__ W1,
                             const float* __restrict__ W2,
                             const float* __restrict__ W3,
                             float* __restrict__ out, int n) {
    // B-fragment SMEM (canonical m16n8k16 col-major B layout, per-lane)
    __shared__ __align__(16) uint32_t sB1hi[2 * 8 * 32 * 2];   // [kt][nt][lane][r]
    __shared__ __align__(16) uint32_t sB1lo[2 * 8 * 32 * 2];
    __shared__ __align__(16) uint32_t sB2hi[4 * 8 * 32 * 2];
    __shared__ __align__(16) uint32_t sB2lo[4 * 8 * 32 * 2];
    __shared__ __align__(16) float    sW3[HID * 4];

    int tid  = threadIdx.x;
    int lane = tid & 31;
    int warp = tid >> 5;
    int g    = lane >> 2;      // fragment row group
    int t    = lane & 3;       // fragment thread-in-group

    // ---- build B fragments once per CTA ----
    for (int idx = tid; idx < 2 * 8 * 32 * 2; idx += TPB) {
        int r = idx & 1, l = (idx >> 1) & 31, nt = (idx >> 6) & 7, kt = idx >> 9;
        int lg = l >> 2, lt = l & 3;
        int nn = 8 * nt + lg;
        int k0 = 16 * kt + 8 * r + 2 * lt;
        float w0 = W1[k0 * HID + nn];
        float w1 = W1[(k0 + 1) * HID + nn];
        sB1hi[idx] = bfp(w0, w1);
        sB1lo[idx] = bfp(bfres(w0), bfres(w1));
    }
    for (int idx = tid; idx < 4 * 8 * 32 * 2; idx += TPB) {
        int r = idx & 1, l = (idx >> 1) & 31, nt = (idx >> 6) & 7, kt = idx >> 9;
        int lg = l >> 2, lt = l & 3;
        int nn = 8 * nt + lg;
        int k0 = 16 * kt + 8 * r + 2 * lt;
        float w0 = W2[k0 * HID + nn];
        float w1 = W2[(k0 + 1) * HID + nn];
        sB2hi[idx] = bfp(w0, w1);
        sB2lo[idx] = bfp(bfres(w0), bfres(w1));
    }
    for (int idx = tid; idx < HID * 4; idx += TPB) sW3[idx] = W3[idx];
    __syncthreads();

    // ---- per-point coords + gather setup (own point = lane) ----
    int i0 = blockIdx.x * TPB + tid;
    int i = min(i0, n - 1);
    float x0 = x[3 * i + 0];
    float x1 = x[3 * i + 1];
    float x2 = x[3 * i + 2];
    bool mask = (fabsf(x0) < 1.0f) && (fabsf(x1) < 1.0f) && (fabsf(x2) < 1.0f);

    float cus[3] = {x0, x1, x2};
    float cvs[3] = {x1, x2, x0};
    unsigned off4[3][4];
    float    wgt[3][4];
    #pragma unroll
    for (int p = 0; p < 3; p++) {
        const float S = 0.5f * (float)(GRID_N - 1);
        float u = fminf(fmaxf(fmaf(cus[p], S, S), 0.0f), (float)(GRID_N - 1));
        float v = fminf(fmaxf(fmaf(cvs[p], S, S), 0.0f), (float)(GRID_N - 1));
        float fu = floorf(u), fv = floorf(v);
        int u0 = (int)fu, v0 = (int)fv;
        int u1 = min(u0 + 1, GRID_N - 1);
        int v1 = min(v0 + 1, GRID_N - 1);
        float wu = u - fu, wv = v - fv;
        wgt[p][0] = (1.0f - wu) * (1.0f - wv);
        wgt[p][1] = (1.0f - wu) * wv;
        wgt[p][2] = wu * (1.0f - wv);
        wgt[p][3] = wu * wv;
        off4[p][0] = (unsigned)((u0 * GRID_N + v0) * (NF / 4));
        off4[p][1] = (unsigned)((u0 * GRID_N + v1) * (NF / 4));
        off4[p][2] = (unsigned)((u1 * GRID_N + v0) * (NF / 4));
        off4[p][3] = (unsigned)((u1 * GRID_N + v1) * (NF / 4));
    }

    // ---- warp-cooperative coalesced gather (R6 verbatim) ----
    const float4* bases[3] = {(const float4*)pzh, (const float4*)phw, (const float4*)pzw};
    float* fWarp = smemDyn + warp * 32 * FSTR;
    int jj = lane >> 3;
    int kk = lane & 7;
    #pragma unroll
    for (int tt = 0; tt < 8; tt++) {
        int src = 4 * tt + jj;
        float4 acc;
        #pragma unroll
        for (int p = 0; p < 3; p++) {
            float4 pf;
            #pragma unroll
            for (int c = 0; c < 4; c++) {
                unsigned o = __shfl_sync(FULLMASK, off4[p][c], src);
                float    w = __shfl_sync(FULLMASK, wgt[p][c], src);
                float4 d = __ldg(bases[p] + o + kk);
                if (c == 0) {
                    pf.x = w * d.x; pf.y = w * d.y; pf.z = w * d.z; pf.w = w * d.w;
                } else {
                    pf.x = fmaf(w, d.x, pf.x); pf.y = fmaf(w, d.y, pf.y);
                    pf.z = fmaf(w, d.z, pf.z); pf.w = fmaf(w, d.w, pf.w);
                }
            }
            if (p == 0) acc = pf;
            else { acc.x *= pf.x; acc.y *= pf.y; acc.z *= pf.z; acc.w *= pf.w; }
        }
        *(float4*)(fWarp + src * FSTR + kk * 4) = acc;
    }
    fWarp[lane * FSTR + 32] = mask ? 1.0f : 0.0f;   // mask flag for this point
    __syncwarp();

    // ---- tensor-core MLP: two 16-row tiles per warp ----
    #pragma unroll
    for (int mt = 0; mt < 2; mt++) {
        int base = 16 * mt;

        // A1 fragments (hi/lo) from feat tile
        uint32_t a1hi[2][4], a1lo[2][4];
        #pragma unroll
        for (int kt = 0; kt < 2; kt++) {
            float2 v0 = *(const float2*)(fWarp + (base + g)     * FSTR + 16 * kt + 2 * t);
            float2 v1 = *(const float2*)(fWarp + (base + g + 8) * FSTR + 16 * kt + 2 * t);
            float2 v2 = *(const float2*)(fWarp + (base + g)     * FSTR + 16 * kt + 8 + 2 * t);
            float2 v3 = *(const float2*)(fWarp + (base + g + 8) * FSTR + 16 * kt + 8 + 2 * t);
            a1hi[kt][0] = bfp(v0.x, v0.y); a1lo[kt][0] = bfp(bfres(v0.x), bfres(v0.y));
            a1hi[kt][1] = bfp(v1.x, v1.y); a1lo[kt][1] = bfp(bfres(v1.x), bfres(v1.y));
            a1hi[kt][2] = bfp(v2.x, v2.y); a1lo[kt][2] = bfp(bfres(v2.x), bfres(v2.y));
            a1hi[kt][3] = bfp(v3.x, v3.y); a1lo[kt][3] = bfp(bfres(v3.x), bfres(v3.y));
        }

        // Layer 1: H[32x64] (this tile: 16 rows), 8 n-tiles
        float H[8][4];
        #pragma unroll
        for (int nt = 0; nt < 8; nt++) {
            float d0 = 0.0f, d1 = 0.0f, d2 = 0.0f, d3 = 0.0f;
            #pragma unroll
            for (int kt = 0; kt < 2; kt++) {
                uint2 bh = *(const uint2*)&sB1hi[((kt * 8 + nt) * 32 + lane) * 2];
                uint2 bl = *(const uint2*)&sB1lo[((kt * 8 + nt) * 32 + lane) * 2];
                MMA_BF16(d0, d1, d2, d3, a1hi[kt][0], a1hi[kt][1], a1hi[kt][2], a1hi[kt][3], bh.x, bh.y);
                MMA_BF16(d0, d1, d2, d3, a1hi[kt][0], a1hi[kt][1], a1hi[kt][2], a1hi[kt][3], bl.x, bl.y);
                MMA_BF16(d0, d1, d2, d3, a1lo[kt][0], a1lo[kt][1], a1lo[kt][2], a1lo[kt][3], bh.x, bh.y);
            }
            H[nt][0] = d0; H[nt][1] = d1; H[nt][2] = d2; H[nt][3] = d3;
        }

        // relu + repack D->A fragments for layer 2 (hi/lo)
        uint32_t a2hi[4][4], a2lo[4][4];
        #pragma unroll
        for (int kt = 0; kt < 4; kt++) {
            float h00 = fmaxf(H[2 * kt][0], 0.0f),     h01 = fmaxf(H[2 * kt][1], 0.0f);
            float h02 = fmaxf(H[2 * kt][2], 0.0f),     h03 = fmaxf(H[2 * kt][3], 0.0f);
            float h10 = fmaxf(H[2 * kt + 1][0], 0.0f), h11 = fmaxf(H[2 * kt + 1][1], 0.0f);
            float h12 = fmaxf(H[2 * kt + 1][2], 0.0f), h13 = fmaxf(H[2 * kt + 1][3], 0.0f);
            a2hi[kt][0] = bfp(h00, h01); a2lo[kt][0] = bfp(bfres(h00), bfres(h01));
            a2hi[kt][1] = bfp(h02, h03); a2lo[kt][1] = bfp(bfres(h02), bfres(h03));
            a2hi[kt][2] = bfp(h10, h11); a2lo[kt][2] = bfp(bfres(h10), bfres(h11));
            a2hi[kt][3] = bfp(h12, h13); a2lo[kt][3] = bfp(bfres(h12), bfres(h13));
        }

        // Layer 2 + fused layer 3 partials
        float o[8] = {0.0f, 0.0f, 0.0f, 0.0f, 0.0f, 0.0f, 0.0f, 0.0f};
        #pragma unroll
        for (int nt = 0; nt < 8; nt++) {
            float d0 = 0.0f, d1 = 0.0f, d2 = 0.0f, d3 = 0.0f;
            #pragma unroll
            for (int kt = 0; kt < 4; kt++) {
                uint2 bh = *(const uint2*)&sB2hi[((kt * 8 + nt) * 32 + lane) * 2];
                uint2 bl = *(const uint2*)&sB2lo[((kt * 8 + nt) * 32 + lane) * 2];
                MMA_BF16(d0, d1, d2, d3, a2hi[kt][0], a2hi[kt][1], a2hi[kt][2], a2hi[kt][3], bh.x, bh.y);
                MMA_BF16(d0, d1, d2, d3, a2hi[kt][0], a2hi[kt][1], a2hi[kt][2], a2hi[kt][3], bl.x, bl.y);
                MMA_BF16(d0, d1, d2, d3, a2lo[kt][0], a2lo[kt][1], a2lo[kt][2], a2lo[kt][3], bh.x, bh.y);
            }
            // layer 3: thread holds h2 of rows g,g+8 at cols c,c+1
            int c = 8 * nt + 2 * t;
            float4 w3a = *(const float4*)(sW3 + c * 4);
            float4 w3b = *(const float4*)(sW3 + (c + 1) * 4);
            float h0 = fmaxf(d0, 0.0f), h1 = fmaxf(d1, 0.0f);
            float h2 = fmaxf(d2, 0.0f), h3 = fmaxf(d3, 0.0f);
            o[0] = fmaf(h0, w3a.x, fmaf(h1, w3b.x, o[0]));
            o[1] = fmaf(h0, w3a.y, fmaf(h1, w3b.y, o[1]));
            o[2] = fmaf(h0, w3a.z, fmaf(h1, w3b.z, o[2]));
            o[3] = fmaf(h0, w3a.w, fmaf(h1, w3b.w, o[3]));
            o[4] = fmaf(h2, w3a.x, fmaf(h3, w3b.x, o[4]));
            o[5] = fmaf(h2, w3a.y, fmaf(h3, w3b.y, o[5]));
            o[6] = fmaf(h2, w3a.z, fmaf(h3, w3b.z, o[6]));
            o[7] = fmaf(h2, w3a.w, fmaf(h3, w3b.w, o[7]));
        }
        // reduce across the 4 threads of the group
        #pragma unroll
        for (int off = 1; off <= 2; off <<= 1) {
            #pragma unroll
            for (int q = 0; q < 8; q++)
                o[q] += __shfl_xor_sync(FULLMASK, o[q], off);
        }

        // t==0 writes row g; t==1 writes row g+8
        if (t < 2) {
            int prow = base + g + 8 * t;
            const float* ov = o + 4 * t;
            int p = blockIdx.x * TPB + warp * 32 + prow;
            if (p < n) {
                bool m = fWarp[prow * FSTR + 32] > 0.5f;
                float c0 = m ? 1.0f / (1.0f + __expf(-ov[0])) : 0.0f;
                float c1 = m ? 1.0f / (1.0f + __expf(-ov[1])) : 0.0f;
                float c2 = m ? 1.0f / (1.0f + __expf(-ov[2])) : 0.0f;
                float sg = m ? __expf(ov[3]) : 0.0f;
                out[3 * p + 0] = c0;
                out[3 * p + 1] = c1;
                out[3 * p + 2] = c2;
                out[3 * n + p] = sg;
            }
        }
    }
}

extern "C" void kernel_launch(void* const* d_in, const int* in_sizes, int n_in,
                              void* d_out, int out_size) {
    const float* x   = (const float*)d_in[0];  // [N,3]
    const float* pzh = (const float*)d_in[1];  // [512,512,32]
    const float* phw = (const float*)d_in[2];
    const float* pzw = (const float*)d_in[3];
    const float* W1  = (const float*)d_in[4];  // [32,64]
    const float* W2  = (const float*)d_in[5];  // [64,64]
    const float* W3  = (const float*)d_in[6];  // [64,4]
    float* out = (float*)d_out;

    int n = in_sizes[0] / 3;
    int blocks = (n + TPB - 1) / TPB;

    size_t smem = (size_t)(8 * 32 * FSTR) * sizeof(float);
    cudaFuncSetAttribute(triplane_decoder_kernel,
                         cudaFuncAttributeMaxDynamicSharedMemorySize, (int)smem);
    triplane_decoder_kernel<<<blocks, TPB, smem>>>(x, pzh, phw, pzw, W1, W2, W3, out, n);
}

// round 16
// speedup vs baseline: 3.0969x; 1.1148x over previous
#include <cuda_runtime.h>
#include <cuda_bf16.h>
#include <cstdint>

// TriplaneDecoder R15 = R14 (tensor-pipe MLP, 414us) with spill elimination:
// layer-1 outputs repacked into layer-2 A-fragments incrementally (H[8][4]
// never live) and B fragments stored hi/lo-interleaved as uint4 (LDS.128).
// Gather = R6 warp-coop coalesced. Output: [c (N*3), sigma (N)].

#define GRID_N   512
#define NF       32
#define HID      64
#define TPB      256
#define FSTR     36            // feat tile row stride (col 32 = mask flag)
#define FULLMASK 0xffffffffu

__device__ __forceinline__ uint32_t bfp(float a, float b) {
    unsigned short ha = __bfloat16_as_ushort(__float2bfloat16(a));
    unsigned short hb = __bfloat16_as_ushort(__float2bfloat16(b));
    return (uint32_t)ha | ((uint32_t)hb << 16);
}
__device__ __forceinline__ float bfres(float a) {
    return a - __bfloat162float(__float2bfloat16(a));
}

#define MMA_BF16(d0, d1, d2, d3, a0, a1, a2, a3, b0, b1)                      \
    asm volatile("mma.sync.aligned.m16n8k16.row.col.f32.bf16.bf16.f32 "       \
        "{%0,%1,%2,%3}, {%4,%5,%6,%7}, {%8,%9}, {%0,%1,%2,%3};"               \
        : "+f"(d0), "+f"(d1), "+f"(d2), "+f"(d3)                              \
        : "r"(a0), "r"(a1), "r"(a2), "r"(a3), "r"(b0), "r"(b1))

extern __shared__ float smemDyn[];   // feat tile: 8 warps * 32 * FSTR floats

__global__ __launch_bounds__(TPB, 2)
void triplane_decoder_kernel(const float* __restrict__ x,
                             const float* __restrict__ pzh,
                             const float* __restrict__ phw,
                             const float* __restrict__ pzw,
                             const float* __restrict__ W1,
                             const float* __restrict__ W2,
                             const float* __restrict__ W3,
                             float* __restrict__ out, int n) {
    // B fragments, hi/lo interleaved: {hi_r0, hi_r1, lo_r0, lo_r1} per lane
    __shared__ __align__(16) uint4 sB1[2 * 8 * 32];   // [kt][nt][lane]
    __shared__ __align__(16) uint4 sB2[4 * 8 * 32];
    __shared__ __align__(16) float sW3[HID * 4];

    int tid  = threadIdx.x;
    int lane = tid & 31;
    int warp = tid >> 5;
    int g    = lane >> 2;      // fragment row group
    int t    = lane & 3;       // fragment thread-in-group

    // ---- build B fragments once per CTA ----
    for (int idx = tid; idx < 2 * 8 * 32; idx += TPB) {
        int l = idx & 31, nt = (idx >> 5) & 7, kt = idx >> 8;
        int lg = l >> 2, lt = l & 3;
        int nn = 8 * nt + lg;
        int k0 = 16 * kt + 2 * lt;
        float w00 = W1[k0 * HID + nn],       w01 = W1[(k0 + 1) * HID + nn];
        float w10 = W1[(k0 + 8) * HID + nn], w11 = W1[(k0 + 9) * HID + nn];
        sB1[idx] = make_uint4(bfp(w00, w01), bfp(w10, w11),
                              bfp(bfres(w00), bfres(w01)), bfp(bfres(w10), bfres(w11)));
    }
    for (int idx = tid; idx < 4 * 8 * 32; idx += TPB) {
        int l = idx & 31, nt = (idx >> 5) & 7, kt = idx >> 8;
        int lg = l >> 2, lt = l & 3;
        int nn = 8 * nt + lg;
        int k0 = 16 * kt + 2 * lt;
        float w00 = W2[k0 * HID + nn],       w01 = W2[(k0 + 1) * HID + nn];
        float w10 = W2[(k0 + 8) * HID + nn], w11 = W2[(k0 + 9) * HID + nn];
        sB2[idx] = make_uint4(bfp(w00, w01), bfp(w10, w11),
                              bfp(bfres(w00), bfres(w01)), bfp(bfres(w10), bfres(w11)));
    }
    for (int idx = tid; idx < HID * 4; idx += TPB) sW3[idx] = W3[idx];
    __syncthreads();

    // ---- per-point coords + gather setup (own point = lane) ----
    int i0 = blockIdx.x * TPB + tid;
    int i = min(i0, n - 1);
    float x0 = x[3 * i + 0];
    float x1 = x[3 * i + 1];
    float x2 = x[3 * i + 2];
    bool mask = (fabsf(x0) < 1.0f) && (fabsf(x1) < 1.0f) && (fabsf(x2) < 1.0f);

    float cus[3] = {x0, x1, x2};
    float cvs[3] = {x1, x2, x0};
    unsigned off4[3][4];
    float    wgt[3][4];
    #pragma unroll
    for (int p = 0; p < 3; p++) {
        const float S = 0.5f * (float)(GRID_N - 1);
        float u = fminf(fmaxf(fmaf(cus[p], S, S), 0.0f), (float)(GRID_N - 1));
        float v = fminf(fmaxf(fmaf(cvs[p], S, S), 0.0f), (float)(GRID_N - 1));
        float fu = floorf(u), fv = floorf(v);
        int u0 = (int)fu, v0 = (int)fv;
        int u1 = min(u0 + 1, GRID_N - 1);
        int v1 = min(v0 + 1, GRID_N - 1);
        float wu = u - fu, wv = v - fv;
        wgt[p][0] = (1.0f - wu) * (1.0f - wv);
        wgt[p][1] = (1.0f - wu) * wv;
        wgt[p][2] = wu * (1.0f - wv);
        wgt[p][3] = wu * wv;
        off4[p][0] = (unsigned)((u0 * GRID_N + v0) * (NF / 4));
        off4[p][1] = (unsigned)((u0 * GRID_N + v1) * (NF / 4));
        off4[p][2] = (unsigned)((u1 * GRID_N + v0) * (NF / 4));
        off4[p][3] = (unsigned)((u1 * GRID_N + v1) * (NF / 4));
    }

    // ---- warp-cooperative coalesced gather (R6 verbatim) ----
    const float4* bases[3] = {(const float4*)pzh, (const float4*)phw, (const float4*)pzw};
    float* fWarp = smemDyn + warp * 32 * FSTR;
    int jj = lane >> 3;
    int kk = lane & 7;
    #pragma unroll
    for (int tt = 0; tt < 8; tt++) {
        int src = 4 * tt + jj;
        float4 acc;
        #pragma unroll
        for (int p = 0; p < 3; p++) {
            float4 pf;
            #pragma unroll
            for (int c = 0; c < 4; c++) {
                unsigned o = __shfl_sync(FULLMASK, off4[p][c], src);
                float    w = __shfl_sync(FULLMASK, wgt[p][c], src);
                float4 d = __ldg(bases[p] + o + kk);
                if (c == 0) {
                    pf.x = w * d.x; pf.y = w * d.y; pf.z = w * d.z; pf.w = w * d.w;
                } else {
                    pf.x = fmaf(w, d.x, pf.x); pf.y = fmaf(w, d.y, pf.y);
                    pf.z = fmaf(w, d.z, pf.z); pf.w = fmaf(w, d.w, pf.w);
                }
            }
            if (p == 0) acc = pf;
            else { acc.x *= pf.x; acc.y *= pf.y; acc.z *= pf.z; acc.w *= pf.w; }
        }
        *(float4*)(fWarp + src * FSTR + kk * 4) = acc;
    }
    fWarp[lane * FSTR + 32] = mask ? 1.0f : 0.0f;
    __syncwarp();

    // ---- tensor-core MLP: two 16-row tiles per warp ----
    #pragma unroll
    for (int mt = 0; mt < 2; mt++) {
        int base = 16 * mt;

        // A1 fragments (hi/lo) from feat tile
        uint32_t a1hi[2][4], a1lo[2][4];
        #pragma unroll
        for (int kt = 0; kt < 2; kt++) {
            float2 v0 = *(const float2*)(fWarp + (base + g)     * FSTR + 16 * kt + 2 * t);
            float2 v1 = *(const float2*)(fWarp + (base + g + 8) * FSTR + 16 * kt + 2 * t);
            float2 v2 = *(const float2*)(fWarp + (base + g)     * FSTR + 16 * kt + 8 + 2 * t);
            float2 v3 = *(const float2*)(fWarp + (base + g + 8) * FSTR + 16 * kt + 8 + 2 * t);
            a1hi[kt][0] = bfp(v0.x, v0.y); a1lo[kt][0] = bfp(bfres(v0.x), bfres(v0.y));
            a1hi[kt][1] = bfp(v1.x, v1.y); a1lo[kt][1] = bfp(bfres(v1.x), bfres(v1.y));
            a1hi[kt][2] = bfp(v2.x, v2.y); a1lo[kt][2] = bfp(bfres(v2.x), bfres(v2.y));
            a1hi[kt][3] = bfp(v3.x, v3.y); a1lo[kt][3] = bfp(bfres(v3.x), bfres(v3.y));
        }

        // Layer 1 in nt-pairs, immediately repacked into layer-2 A fragments
        uint32_t a2hi[4][4], a2lo[4][4];
        #pragma unroll
        for (int q2 = 0; q2 < 4; q2++) {
            float dA0 = 0.0f, dA1 = 0.0f, dA2 = 0.0f, dA3 = 0.0f;
            float dB0 = 0.0f, dB1 = 0.0f, dB2 = 0.0f, dB3 = 0.0f;
            #pragma unroll
            for (int kt = 0; kt < 2; kt++) {
                uint4 bA = sB1[(kt * 8 + 2 * q2) * 32 + lane];
                MMA_BF16(dA0, dA1, dA2, dA3, a1hi[kt][0], a1hi[kt][1], a1hi[kt][2], a1hi[kt][3], bA.x, bA.y);
                MMA_BF16(dA0, dA1, dA2, dA3, a1hi[kt][0], a1hi[kt][1], a1hi[kt][2], a1hi[kt][3], bA.z, bA.w);
                MMA_BF16(dA0, dA1, dA2, dA3, a1lo[kt][0], a1lo[kt][1], a1lo[kt][2], a1lo[kt][3], bA.x, bA.y);
                uint4 bB = sB1[(kt * 8 + 2 * q2 + 1) * 32 + lane];
                MMA_BF16(dB0, dB1, dB2, dB3, a1hi[kt][0], a1hi[kt][1], a1hi[kt][2], a1hi[kt][3], bB.x, bB.y);
                MMA_BF16(dB0, dB1, dB2, dB3, a1hi[kt][0], a1hi[kt][1], a1hi[kt][2], a1hi[kt][3], bB.z, bB.w);
                MMA_BF16(dB0, dB1, dB2, dB3, a1lo[kt][0], a1lo[kt][1], a1lo[kt][2], a1lo[kt][3], bB.x, bB.y);
            }
            float hA0 = fmaxf(dA0, 0.0f), hA1 = fmaxf(dA1, 0.0f);
            float hA2 = fmaxf(dA2, 0.0f), hA3 = fmaxf(dA3, 0.0f);
            float hB0 = fmaxf(dB0, 0.0f), hB1 = fmaxf(dB1, 0.0f);
            float hB2 = fmaxf(dB2, 0.0f), hB3 = fmaxf(dB3, 0.0f);
            a2hi[q2][0] = bfp(hA0, hA1); a2lo[q2][0] = bfp(bfres(hA0), bfres(hA1));
            a2hi[q2][1] = bfp(hA2, hA3); a2lo[q2][1] = bfp(bfres(hA2), bfres(hA3));
            a2hi[q2][2] = bfp(hB0, hB1); a2lo[q2][2] = bfp(bfres(hB0), bfres(hB1));
            a2hi[q2][3] = bfp(hB2, hB3); a2lo[q2][3] = bfp(bfres(hB2), bfres(hB3));
        }

        // Layer 2 + fused layer 3 partials
        float o[8] = {0.0f, 0.0f, 0.0f, 0.0f, 0.0f, 0.0f, 0.0f, 0.0f};
        #pragma unroll
        for (int nt = 0; nt < 8; nt++) {
            float d0 = 0.0f, d1 = 0.0f, d2 = 0.0f, d3 = 0.0f;
            #pragma unroll
            for (int kt = 0; kt < 4; kt++) {
                uint4 b = sB2[(kt * 8 + nt) * 32 + lane];
                MMA_BF16(d0, d1, d2, d3, a2hi[kt][0], a2hi[kt][1], a2hi[kt][2], a2hi[kt][3], b.x, b.y);
                MMA_BF16(d0, d1, d2, d3, a2hi[kt][0], a2hi[kt][1], a2hi[kt][2], a2hi[kt][3], b.z, b.w);
                MMA_BF16(d0, d1, d2, d3, a2lo[kt][0], a2lo[kt][1], a2lo[kt][2], a2lo[kt][3], b.x, b.y);
            }
            int c = 8 * nt + 2 * t;
            float4 w3a = *(const float4*)(sW3 + c * 4);
            float4 w3b = *(const float4*)(sW3 + (c + 1) * 4);
            float h0 = fmaxf(d0, 0.0f), h1 = fmaxf(d1, 0.0f);
            float h2 = fmaxf(d2, 0.0f), h3 = fmaxf(d3, 0.0f);
            o[0] = fmaf(h0, w3a.x, fmaf(h1, w3b.x, o[0]));
            o[1] = fmaf(h0, w3a.y, fmaf(h1, w3b.y, o[1]));
            o[2] = fmaf(h0, w3a.z, fmaf(h1, w3b.z, o[2]));
            o[3] = fmaf(h0, w3a.w, fmaf(h1, w3b.w, o[3]));
            o[4] = fmaf(h2, w3a.x, fmaf(h3, w3b.x, o[4]));
            o[5] = fmaf(h2, w3a.y, fmaf(h3, w3b.y, o[5]));
            o[6] = fmaf(h2, w3a.z, fmaf(h3, w3b.z, o[6]));
            o[7] = fmaf(h2, w3a.w, fmaf(h3, w3b.w, o[7]));
        }
        #pragma unroll
        for (int off = 1; off <= 2; off <<= 1) {
            #pragma unroll
            for (int q = 0; q < 8; q++)
                o[q] += __shfl_xor_sync(FULLMASK, o[q], off);
        }

        if (t < 2) {
            int prow = base + g + 8 * t;
            const float* ov = o + 4 * t;
            int p = blockIdx.x * TPB + warp * 32 + prow;
            if (p < n) {
                bool m = fWarp[prow * FSTR + 32] > 0.5f;
                float c0 = m ? 1.0f / (1.0f + __expf(-ov[0])) : 0.0f;
                float c1 = m ? 1.0f / (1.0f + __expf(-ov[1])) : 0.0f;
                float c2 = m ? 1.0f / (1.0f + __expf(-ov[2])) : 0.0f;
                float sg = m ? __expf(ov[3]) : 0.0f;
                out[3 * p + 0] = c0;
                out[3 * p + 1] = c1;
                out[3 * p + 2] = c2;
                out[3 * n + p] = sg;
            }
        }
    }
}

extern "C" void kernel_launch(void* const* d_in, const int* in_sizes, int n_in,
                              void* d_out, int out_size) {
    const float* x   = (const float*)d_in[0];  // [N,3]
    const float* pzh = (const float*)d_in[1];  // [512,512,32]
    const float* phw = (const float*)d_in[2];
    const float* pzw = (const float*)d_in[3];
    const float* W1  = (const float*)d_in[4];  // [32,64]
    const float* W2  = (const float*)d_in[5];  // [64,64]
    const float* W3  = (const float*)d_in[6];  // [64,4]
    float* out = (float*)d_out;

    int n = in_sizes[0] / 3;
    int blocks = (n + TPB - 1) / TPB;

    size_t smem = (size_t)(8 * 32 * FSTR) * sizeof(float);
    cudaFuncSetAttribute(triplane_decoder_kernel,
                         cudaFuncAttributeMaxDynamicSharedMemorySize, (int)smem);
    triplane_decoder_kernel<<<blocks, TPB, smem>>>(x, pzh, phw, pzw, W1, W2, W3, out, n);
}